// round 10
// baseline (speedup 1.0000x reference)
#include <cuda_runtime.h>
#include <cuda_bf16.h>
#include <math.h>
#include <stdint.h>

// ---------------------------------------------------------------------------
// BiLSTM: B=32, T=512, D=512, H=512.
//   prep_w / prep_whh / prep_x: bf16 split (hi + lo)
//   xg_mma: HMMA bf16 3-split GEMM -> g_xg[dir][t][g][b]      (R8, passing)
//   rec_kernel: persistent HMMA recurrence; per-warp producer polling,
//               per-warp k-slice staging, triple-buffered h exchange.
// ---------------------------------------------------------------------------

#define BB 32
#define TT 512
#define DD 512
#define HH 512
#define G4 2048
#define NBLK 128

typedef unsigned long long ull;

__device__ float g_xg[(size_t)2 * TT * G4 * BB];      // [dir][t][g][b]
__device__ __nv_bfloat16 g_hb[3 * 2 * 2 * 32 * 512];  // [buf3][dir][split][b][512]
__device__ int   g_flags[NBLK];
__device__ __nv_bfloat16 g_Whi[(size_t)2 * G4 * DD];
__device__ __nv_bfloat16 g_Wlo[(size_t)2 * G4 * DD];
__device__ __nv_bfloat16 g_Hhi[(size_t)2 * G4 * HH];
__device__ __nv_bfloat16 g_Hlo[(size_t)2 * G4 * HH];
__device__ __nv_bfloat16 g_xhi[(size_t)BB * TT * DD];
__device__ __nv_bfloat16 g_xlo[(size_t)BB * TT * DD];

__device__ __forceinline__ float sigmoidf_(float x) {
    return 1.0f / (1.0f + expf(-x));
}
__device__ __forceinline__ void cpa16(uint32_t s, const void* g) {
    asm volatile("cp.async.cg.shared.global [%0], [%1], 16;" :: "r"(s), "l"(g));
}
__device__ __forceinline__ void cpa_commit() {
    asm volatile("cp.async.commit_group;");
}
template <int N> __device__ __forceinline__ void cpa_wait() {
    asm volatile("cp.async.wait_group %0;" :: "n"(N));
}
__device__ __forceinline__ uint32_t smem_u32(const void* p) {
    return (uint32_t)__cvta_generic_to_shared(p);
}
__device__ __forceinline__ void ldsm4(uint32_t* r, uint32_t a) {
    asm volatile("ldmatrix.sync.aligned.m8n8.x4.shared.b16 {%0,%1,%2,%3}, [%4];"
                 : "=r"(r[0]), "=r"(r[1]), "=r"(r[2]), "=r"(r[3]) : "r"(a));
}
__device__ __forceinline__ void mma16816(float* c, const uint32_t* a,
                                         const uint32_t* b) {
    asm volatile(
        "mma.sync.aligned.m16n8k16.row.col.f32.bf16.bf16.f32 "
        "{%0,%1,%2,%3}, {%4,%5,%6,%7}, {%8,%9}, {%0,%1,%2,%3};"
        : "+f"(c[0]), "+f"(c[1]), "+f"(c[2]), "+f"(c[3])
        : "r"(a[0]), "r"(a[1]), "r"(a[2]), "r"(a[3]), "r"(b[0]), "r"(b[1]));
}

// ---------------------------------------------------------------------------
__global__ void init_kernel() {
    int i = blockIdx.x * blockDim.x + threadIdx.x;
    if (i < NBLK) g_flags[i] = 0;
    if (i < 32768) ((uint32_t*)g_hb)[i] = 0u;   // zero h buffer 0 (131072 B)
}

// ---------------------------------------------------------------------------
// bf16 split preps
// ---------------------------------------------------------------------------
__global__ void prep_w(const float* __restrict__ Wf, const float* __restrict__ Wb) {
    size_t i = (size_t)blockIdx.x * 256 + threadIdx.x;
    const size_t half = (size_t)G4 * DD;
    if (i >= 2 * half) return;
    float w = (i < half) ? Wf[i] : Wb[i - half];
    __nv_bfloat16 hi = __float2bfloat16(w);
    g_Whi[i] = hi;
    g_Wlo[i] = __float2bfloat16(w - __bfloat162float(hi));
}
__global__ void prep_whh(const float* __restrict__ Wf, const float* __restrict__ Wb) {
    size_t i = (size_t)blockIdx.x * 256 + threadIdx.x;
    const size_t half = (size_t)G4 * HH;
    if (i >= 2 * half) return;
    float w = (i < half) ? Wf[i] : Wb[i - half];
    __nv_bfloat16 hi = __float2bfloat16(w);
    g_Hhi[i] = hi;
    g_Hlo[i] = __float2bfloat16(w - __bfloat162float(hi));
}
__global__ void prep_x(const float* __restrict__ x) {
    size_t i = (size_t)blockIdx.x * 256 + threadIdx.x;
    if (i >= (size_t)BB * TT * DD) return;
    float v = x[i];
    __nv_bfloat16 hi = __float2bfloat16(v);
    g_xhi[i] = hi;
    g_xlo[i] = __float2bfloat16(v - __bfloat162float(hi));
}

// ---------------------------------------------------------------------------
// xg_mma (R8 version, passing): block = 128 gates x 64 N (2t x 32b), K=512.
// ---------------------------------------------------------------------------
#define XG_BUF 55296
#define XG_AROWB 144

__device__ __forceinline__ void xg_issue(uint32_t bbase, int kc, int gbase,
                                         const __nv_bfloat16* __restrict__ Whi,
                                         const __nv_bfloat16* __restrict__ Wlo,
                                         int t0, int tid) {
    int k0 = kc * 64;
#pragma unroll
    for (int i = tid; i < 3072; i += 256) {
        if (i < 2048) {
            int split = i >> 10, idx = i & 1023;
            int row = idx >> 3, seg = idx & 7;
            const __nv_bfloat16* src =
                (split ? Wlo : Whi) + (size_t)(gbase + row) * DD + k0 + seg * 8;
            cpa16(bbase + split * 18432 + row * XG_AROWB + seg * 16, src);
        } else {
            int j = i - 2048;
            int split = j >> 9, idx = j & 511;
            int row = idx >> 3, seg = idx & 7;
            int t = t0 + (row >> 5), b = row & 31;
            const __nv_bfloat16* src =
                (split ? g_xlo : g_xhi) + ((size_t)b * TT + t) * DD + k0 + seg * 8;
            cpa16(bbase + 36864 + split * 9216 + row * XG_AROWB + seg * 16, src);
        }
    }
}

__global__ void __launch_bounds__(256, 1)
xg_mma(const float* __restrict__ bihf, const float* __restrict__ bhhf,
       const float* __restrict__ bihb, const float* __restrict__ bhhb) {
    extern __shared__ unsigned char dsm[];
    int tid = threadIdx.x, wid = tid >> 5, lane = tid & 31;
    int nt = blockIdx.x, mb = blockIdx.y;
    int dir = mb >> 4, gbase = (mb & 15) * 128;
    int t0 = nt * 2;
    int warp_m = wid >> 1, warp_n = wid & 1;
    const __nv_bfloat16* Whi = g_Whi + (size_t)dir * G4 * DD;
    const __nv_bfloat16* Wlo = g_Wlo + (size_t)dir * G4 * DD;
    const float* bih = dir ? bihb : bihf;
    const float* bhh = dir ? bhhb : bhhf;

    float c[2][4][4];
#pragma unroll
    for (int mi = 0; mi < 2; mi++)
#pragma unroll
        for (int j = 0; j < 4; j++)
#pragma unroll
            for (int q = 0; q < 4; q++) c[mi][j][q] = 0.f;

    uint32_t sbase = smem_u32(dsm);
    int quad = lane >> 3, qr = lane & 7;
    int aRow = warp_m * 32 + (quad & 1) * 8 + qr;
    int colA = (quad >> 1) * 8;
    int bRow0 = warp_n * 32 + (quad >> 1) * 8 + qr;
    int bRow1 = bRow0 + 16;
    int colB = (quad & 1) * 8;

    xg_issue(sbase, 0, gbase, Whi, Wlo, t0, tid);
    cpa_commit();

#pragma unroll 1
    for (int kc = 0; kc < 8; kc++) {
        if (kc < 7) {
            xg_issue(sbase + ((kc + 1) & 1) * XG_BUF, kc + 1, gbase, Whi, Wlo, t0, tid);
            cpa_commit();
            cpa_wait<1>();
        } else {
            cpa_wait<0>();
        }
        __syncthreads();

        uint32_t bb = sbase + (kc & 1) * XG_BUF;
        uint32_t aHi = bb + (uint32_t)(aRow * XG_AROWB + colA * 2);
        uint32_t aLo = aHi + 18432;
        uint32_t bHi0 = bb + 36864 + (uint32_t)(bRow0 * XG_AROWB + colB * 2);
        uint32_t bHi1 = bb + 36864 + (uint32_t)(bRow1 * XG_AROWB + colB * 2);
        uint32_t bLo0 = bHi0 + 9216;
        uint32_t bLo1 = bHi1 + 9216;

#pragma unroll
        for (int ks = 0; ks < 4; ks++) {
            uint32_t ah0[4], ah1[4], al0[4], al1[4];
            uint32_t bh0[4], bh1[4], bl0[4], bl1[4];
            ldsm4(ah0, aHi + ks * 32);
            ldsm4(ah1, aHi + 2304 + ks * 32);
            ldsm4(al0, aLo + ks * 32);
            ldsm4(al1, aLo + 2304 + ks * 32);
            ldsm4(bh0, bHi0 + ks * 32);
            ldsm4(bh1, bHi1 + ks * 32);
            ldsm4(bl0, bLo0 + ks * 32);
            ldsm4(bl1, bLo1 + ks * 32);
#pragma unroll
            for (int j = 0; j < 4; j++) {
                const uint32_t* Bh = ((j < 2) ? bh0 : bh1) + (j & 1) * 2;
                const uint32_t* Bl = ((j < 2) ? bl0 : bl1) + (j & 1) * 2;
                mma16816(c[0][j], ah0, Bh);
                mma16816(c[0][j], ah0, Bl);
                mma16816(c[0][j], al0, Bh);
                mma16816(c[1][j], ah1, Bh);
                mma16816(c[1][j], ah1, Bl);
                mma16816(c[1][j], al1, Bh);
            }
        }
        __syncthreads();
    }

    int t = t0 + warp_n;
    float* outp = g_xg + (((size_t)dir * TT + t) * G4 + gbase + warp_m * 32) * 32;
    int tig = lane & 3, grp = lane >> 2;
#pragma unroll
    for (int mi = 0; mi < 2; mi++) {
        int m0 = mi * 16 + grp;
        int gg = gbase + warp_m * 32 + m0;
        float bia0 = bih[gg] + bhh[gg];
        float bia1 = bih[gg + 8] + bhh[gg + 8];
#pragma unroll
        for (int j = 0; j < 4; j++) {
            int b = j * 8 + tig * 2;
            float2 v0 = make_float2(c[mi][j][0] + bia0, c[mi][j][1] + bia0);
            float2 v1 = make_float2(c[mi][j][2] + bia1, c[mi][j][3] + bia1);
            __stcs((float2*)(outp + (size_t)m0 * 32 + b), v0);
            __stcs((float2*)(outp + (size_t)(m0 + 8) * 32 + b), v1);
        }
    }
}

// ---------------------------------------------------------------------------
// rec_kernel: 128 blocks x 256 threads. Block = (dir, 8 units = 32 rows
// r=g*8+u). Warp w = K-slice [64w,64w+64) -> depends on producer blocks
// [8w, 8w+8) of its direction only. Per-warp poll + per-warp 8KB staging.
// h exchange: triple-buffered bf16 hi/lo [b][512] in L2.
// smem: per-warp slices 8x9216 | sC 8x32x40 f32. Prologue reuses region.
// ---------------------------------------------------------------------------
#define RSLICE 9216
#define RSPLIT 4608
#define RROWB  144
#define RSC_OFF 73728
#define HSTR 1040

__global__ void __launch_bounds__(256, 1)
rec_kernel(const int* __restrict__ lengths, float* __restrict__ out) {
    extern __shared__ unsigned char sm[];
    float* sC = (float*)(sm + RSC_OFF);    // [8][32][40]
    __shared__ __nv_bfloat16 sPub[2][32][8];
    __shared__ float sOut[32][8];

    int blk = blockIdx.x;
    int dir = blk >> 6;
    int jbase = (blk & 63) * 8;
    int tid = threadIdx.x, wid = tid >> 5, lane = tid & 31;
    int quad = lane >> 3, qr = lane & 7;
    uint32_t sbase = smem_u32(sm);

    // ---- prologue: stage W_hh rows (hi @0, lo @33280), load A fragments ----
    {
        const __nv_bfloat16* Hhi = g_Hhi + (size_t)dir * G4 * HH;
        const __nv_bfloat16* Hlo = g_Hlo + (size_t)dir * G4 * HH;
        for (int i = tid; i < 2048; i += 256) {
            int row = i >> 6, ch = i & 63;
            int g = row >> 3, u = row & 7;
            size_t src = (size_t)(g * 512 + jbase + u) * HH + ch * 8;
            *(float4*)(sm + row * HSTR + ch * 16) = *(const float4*)(Hhi + src);
            *(float4*)(sm + 33280 + row * HSTR + ch * 16) = *(const float4*)(Hlo + src);
        }
    }
    __syncthreads();

    uint32_t ahi[2][4][4], alo[2][4][4];
#pragma unroll
    for (int mi = 0; mi < 2; mi++) {
#pragma unroll
        for (int kt = 0; kt < 4; kt++) {
            int aRow = mi * 16 + (quad & 1) * 8 + qr;
            int colA = wid * 64 + kt * 16 + (quad >> 1) * 8;
            ldsm4(ahi[mi][kt], sbase + (uint32_t)(aRow * HSTR + colA * 2));
            ldsm4(alo[mi][kt], sbase + 33280 + (uint32_t)(aRow * HSTR + colA * 2));
        }
    }
    __syncthreads();

    int mylen = lengths[lane];
    int j = jbase + wid;                    // pointwise identity (unit, batch)
    float cc = 0.f, hh = 0.f;
    const float* xgd = g_xg + (size_t)dir * TT * G4 * 32;
    int bRow0 = (quad >> 1) * 8 + qr;
    int colB = (quad & 1) * 8;
    int grp = lane >> 2, tig = lane & 3;
    const int fidx = dir * 64 + 8 * wid + (lane & 7);   // this warp's producers
    const uint32_t wslice = sbase + wid * RSLICE;

    for (int s = 0; s < TT; s++) {
        int t = dir ? (TT - 1 - s) : s;
        int rb = s % 3, wb = (s + 1) % 3;

        // xg prefetch for pointwise
        const float* xgt = xgd + (size_t)t * G4 * 32;
        float xv0 = __ldcs(xgt + (size_t)(0 * HH + j) * 32 + lane);
        float xv1 = __ldcs(xgt + (size_t)(1 * HH + j) * 32 + lane);
        float xv2 = __ldcs(xgt + (size_t)(2 * HH + j) * 32 + lane);
        float xv3 = __ldcs(xgt + (size_t)(3 * HH + j) * 32 + lane);

        // per-warp poll: only this warp's 8 producers must have published s
        {
            volatile int* fp = (volatile int*)&g_flags[fidx];
            while (!__all_sync(0xffffffffu, *fp >= s)) { }
        }

        // per-warp slice staging: 2 splits x 32 b x 128 B
        {
            const __nv_bfloat16* hs = g_hb + (size_t)(rb * 2 + dir) * 32768;
#pragma unroll
            for (int i = lane; i < 512; i += 32) {
                int split = i >> 8, idx = i & 255, b = idx >> 3, seg = idx & 7;
                cpa16(wslice + split * RSPLIT + b * RROWB + seg * 16,
                      hs + (size_t)split * 16384 + b * 512 + 64 * wid + seg * 8);
            }
            cpa_commit();
            cpa_wait<0>();
            __syncwarp();
        }

        // MMA over this warp's K-slice, 3-split
        float cf[2][4][4];
#pragma unroll
        for (int mi = 0; mi < 2; mi++)
#pragma unroll
            for (int jj = 0; jj < 4; jj++)
#pragma unroll
                for (int q = 0; q < 4; q++) cf[mi][jj][q] = 0.f;

#pragma unroll
        for (int kt = 0; kt < 4; kt++) {
            uint32_t ba = wslice + (uint32_t)(bRow0 * RROWB + (kt * 16 + colB) * 2);
            uint32_t bh0[4], bh1[4], bl0[4], bl1[4];
            ldsm4(bh0, ba);
            ldsm4(bh1, ba + 16 * RROWB);
            ldsm4(bl0, ba + RSPLIT);
            ldsm4(bl1, ba + RSPLIT + 16 * RROWB);
#pragma unroll
            for (int jj = 0; jj < 4; jj++) {
                const uint32_t* Bh = ((jj < 2) ? bh0 : bh1) + (jj & 1) * 2;
                const uint32_t* Bl = ((jj < 2) ? bl0 : bl1) + (jj & 1) * 2;
                mma16816(cf[0][jj], ahi[0][kt], Bh);
                mma16816(cf[0][jj], ahi[0][kt], Bl);
                mma16816(cf[0][jj], alo[0][kt], Bh);
                mma16816(cf[1][jj], ahi[1][kt], Bh);
                mma16816(cf[1][jj], ahi[1][kt], Bl);
                mma16816(cf[1][jj], alo[1][kt], Bh);
            }
        }

        // store partials sC[w][m][40]
        {
            float* cw = sC + wid * 1280;
#pragma unroll
            for (int mi = 0; mi < 2; mi++) {
#pragma unroll
                for (int jj = 0; jj < 4; jj++) {
                    int m0 = mi * 16 + grp, n0 = jj * 8 + tig * 2;
                    cw[m0 * 40 + n0]           = cf[mi][jj][0];
                    cw[m0 * 40 + n0 + 1]       = cf[mi][jj][1];
                    cw[(m0 + 8) * 40 + n0]     = cf[mi][jj][2];
                    cw[(m0 + 8) * 40 + n0 + 1] = cf[mi][jj][3];
                }
            }
        }
        __syncthreads();

        // pointwise with merged 8-way reduce (thread = (unit wid, batch lane))
        {
            float a0 = 0.f, a1 = 0.f, a2 = 0.f, a3 = 0.f;
#pragma unroll
            for (int w2 = 0; w2 < 8; w2++) {
                const float* cw = sC + w2 * 1280;
                a0 += cw[(0 * 8 + wid) * 40 + lane];
                a1 += cw[(1 * 8 + wid) * 40 + lane];
                a2 += cw[(2 * 8 + wid) * 40 + lane];
                a3 += cw[(3 * 8 + wid) * 40 + lane];
            }
            float gi = sigmoidf_(a0 + xv0);
            float gf = sigmoidf_(a1 + xv1);
            float gg = tanhf   (a2 + xv2);
            float go = sigmoidf_(a3 + xv3);
            float cn = gf * cc + gi * gg;
            float hn = go * tanhf(cn);
            if (t < mylen) { cc = cn; hh = hn; }
            __nv_bfloat16 hi = __float2bfloat16(hh);
            sPub[0][lane][wid] = hi;
            sPub[1][lane][wid] = __float2bfloat16(hh - __bfloat162float(hi));
            sOut[lane][wid] = hh;
        }
        __syncthreads();

        // publish h into write buffer
        if (tid < 64) {
            int split = tid >> 5, b = tid & 31;
            __stcg((float4*)(g_hb + (size_t)(wb * 2 + dir) * 32768
                             + (size_t)split * 16384 + b * 512 + jbase),
                   *(float4*)&sPub[split][b][0]);
        }
        __syncthreads();
        if (tid == 0) {
            __threadfence();
            ((volatile int*)g_flags)[blk] = s + 1;
        }
        if (tid >= 64 && tid < 128) {
            int idx = tid - 64;
            int b = idx >> 1, half = idx & 1;
            float4 v;
            v.x = sOut[b][half * 4 + 0]; v.y = sOut[b][half * 4 + 1];
            v.z = sOut[b][half * 4 + 2]; v.w = sOut[b][half * 4 + 3];
            *(float4*)(out + ((size_t)(b * TT + t)) * 1024 + dir * HH + jbase + half * 4) = v;
        }
    }
}

// ---------------------------------------------------------------------------
extern "C" void kernel_launch(void* const* d_in, const int* in_sizes, int n_in,
                              void* d_out, int out_size) {
    const float* x      = (const float*)d_in[0];
    const int*   lens   = (const int*)  d_in[1];
    const float* W_ih_f = (const float*)d_in[2];
    const float* W_hh_f = (const float*)d_in[3];
    const float* b_ih_f = (const float*)d_in[4];
    const float* b_hh_f = (const float*)d_in[5];
    const float* W_ih_b = (const float*)d_in[6];
    const float* W_hh_b = (const float*)d_in[7];
    const float* b_ih_b = (const float*)d_in[8];
    const float* b_hh_b = (const float*)d_in[9];
    float* out = (float*)d_out;

    cudaFuncSetAttribute(xg_mma,     cudaFuncAttributeMaxDynamicSharedMemorySize, 2 * XG_BUF);
    cudaFuncSetAttribute(rec_kernel, cudaFuncAttributeMaxDynamicSharedMemorySize, 131072);

    init_kernel<<<256, 256>>>();
    prep_w<<<(2 * G4 * DD + 255) / 256, 256>>>(W_ih_f, W_ih_b);
    prep_whh<<<(2 * G4 * HH + 255) / 256, 256>>>(W_hh_f, W_hh_b);
    prep_x<<<(BB * TT * DD + 255) / 256, 256>>>(x);
    xg_mma<<<dim3(256, 32), 256, 2 * XG_BUF>>>(b_ih_f, b_hh_f, b_ih_b, b_hh_b);
    rec_kernel<<<NBLK, 256, 131072>>>(lens, out);
}

// round 12
// speedup vs baseline: 1.0374x; 1.0374x over previous
#include <cuda_runtime.h>
#include <cuda_bf16.h>
#include <math.h>
#include <stdint.h>

// ---------------------------------------------------------------------------
// BiLSTM: B=32, T=512, D=512, H=512.
//   prep_w / prep_whh / prep_x: bf16 split (hi + lo)
//   xg_mma: HMMA bf16 3-split GEMM -> g_xg[dir][t][g][b]      (R8, passing)
//   rec_kernel: R9 structure (global barrier, double-buffered h, block-wide
//     staging) + publisher-scoped fence + merged reduce-into-pointwise.
// ---------------------------------------------------------------------------

#define BB 32
#define TT 512
#define DD 512
#define HH 512
#define G4 2048
#define NBLK 128

typedef unsigned long long ull;

__device__ float g_xg[(size_t)2 * TT * G4 * BB];      // [dir][t][g][b]
__device__ __nv_bfloat16 g_hb[2 * 2 * 2 * 32 * 512];  // [buf][dir][split][b][512]
__device__ int   g_flags[NBLK];
__device__ __nv_bfloat16 g_Whi[(size_t)2 * G4 * DD];
__device__ __nv_bfloat16 g_Wlo[(size_t)2 * G4 * DD];
__device__ __nv_bfloat16 g_Hhi[(size_t)2 * G4 * HH];
__device__ __nv_bfloat16 g_Hlo[(size_t)2 * G4 * HH];
__device__ __nv_bfloat16 g_xhi[(size_t)BB * TT * DD];
__device__ __nv_bfloat16 g_xlo[(size_t)BB * TT * DD];

__device__ __forceinline__ float sigmoidf_(float x) {
    return 1.0f / (1.0f + expf(-x));
}
__device__ __forceinline__ void cpa16(uint32_t s, const void* g) {
    asm volatile("cp.async.cg.shared.global [%0], [%1], 16;" :: "r"(s), "l"(g));
}
__device__ __forceinline__ void cpa_commit() {
    asm volatile("cp.async.commit_group;");
}
template <int N> __device__ __forceinline__ void cpa_wait() {
    asm volatile("cp.async.wait_group %0;" :: "n"(N));
}
__device__ __forceinline__ uint32_t smem_u32(const void* p) {
    return (uint32_t)__cvta_generic_to_shared(p);
}
__device__ __forceinline__ void ldsm4(uint32_t* r, uint32_t a) {
    asm volatile("ldmatrix.sync.aligned.m8n8.x4.shared.b16 {%0,%1,%2,%3}, [%4];"
                 : "=r"(r[0]), "=r"(r[1]), "=r"(r[2]), "=r"(r[3]) : "r"(a));
}
__device__ __forceinline__ void mma16816(float* c, const uint32_t* a,
                                         const uint32_t* b) {
    asm volatile(
        "mma.sync.aligned.m16n8k16.row.col.f32.bf16.bf16.f32 "
        "{%0,%1,%2,%3}, {%4,%5,%6,%7}, {%8,%9}, {%0,%1,%2,%3};"
        : "+f"(c[0]), "+f"(c[1]), "+f"(c[2]), "+f"(c[3])
        : "r"(a[0]), "r"(a[1]), "r"(a[2]), "r"(a[3]), "r"(b[0]), "r"(b[1]));
}

// ---------------------------------------------------------------------------
__global__ void init_kernel() {
    int i = blockIdx.x * blockDim.x + threadIdx.x;
    if (i < NBLK) g_flags[i] = 0;
    ((uint32_t*)g_hb)[i] = 0u;   // 65536 words exactly (256x256 grid)
}

// ---------------------------------------------------------------------------
// bf16 split preps
// ---------------------------------------------------------------------------
__global__ void prep_w(const float* __restrict__ Wf, const float* __restrict__ Wb) {
    size_t i = (size_t)blockIdx.x * 256 + threadIdx.x;
    const size_t half = (size_t)G4 * DD;
    if (i >= 2 * half) return;
    float w = (i < half) ? Wf[i] : Wb[i - half];
    __nv_bfloat16 hi = __float2bfloat16(w);
    g_Whi[i] = hi;
    g_Wlo[i] = __float2bfloat16(w - __bfloat162float(hi));
}
__global__ void prep_whh(const float* __restrict__ Wf, const float* __restrict__ Wb) {
    size_t i = (size_t)blockIdx.x * 256 + threadIdx.x;
    const size_t half = (size_t)G4 * HH;
    if (i >= 2 * half) return;
    float w = (i < half) ? Wf[i] : Wb[i - half];
    __nv_bfloat16 hi = __float2bfloat16(w);
    g_Hhi[i] = hi;
    g_Hlo[i] = __float2bfloat16(w - __bfloat162float(hi));
}
__global__ void prep_x(const float* __restrict__ x) {
    size_t i = (size_t)blockIdx.x * 256 + threadIdx.x;
    if (i >= (size_t)BB * TT * DD) return;
    float v = x[i];
    __nv_bfloat16 hi = __float2bfloat16(v);
    g_xhi[i] = hi;
    g_xlo[i] = __float2bfloat16(v - __bfloat162float(hi));
}

// ---------------------------------------------------------------------------
// xg_mma (R8 version, passing): block = 128 gates x 64 N (2t x 32b), K=512.
// ---------------------------------------------------------------------------
#define XG_BUF 55296
#define XG_AROWB 144

__device__ __forceinline__ void xg_issue(uint32_t bbase, int kc, int gbase,
                                         const __nv_bfloat16* __restrict__ Whi,
                                         const __nv_bfloat16* __restrict__ Wlo,
                                         int t0, int tid) {
    int k0 = kc * 64;
#pragma unroll
    for (int i = tid; i < 3072; i += 256) {
        if (i < 2048) {
            int split = i >> 10, idx = i & 1023;
            int row = idx >> 3, seg = idx & 7;
            const __nv_bfloat16* src =
                (split ? Wlo : Whi) + (size_t)(gbase + row) * DD + k0 + seg * 8;
            cpa16(bbase + split * 18432 + row * XG_AROWB + seg * 16, src);
        } else {
            int j = i - 2048;
            int split = j >> 9, idx = j & 511;
            int row = idx >> 3, seg = idx & 7;
            int t = t0 + (row >> 5), b = row & 31;
            const __nv_bfloat16* src =
                (split ? g_xlo : g_xhi) + ((size_t)b * TT + t) * DD + k0 + seg * 8;
            cpa16(bbase + 36864 + split * 9216 + row * XG_AROWB + seg * 16, src);
        }
    }
}

__global__ void __launch_bounds__(256, 1)
xg_mma(const float* __restrict__ bihf, const float* __restrict__ bhhf,
       const float* __restrict__ bihb, const float* __restrict__ bhhb) {
    extern __shared__ unsigned char dsm[];
    int tid = threadIdx.x, wid = tid >> 5, lane = tid & 31;
    int nt = blockIdx.x, mb = blockIdx.y;
    int dir = mb >> 4, gbase = (mb & 15) * 128;
    int t0 = nt * 2;
    int warp_m = wid >> 1, warp_n = wid & 1;
    const __nv_bfloat16* Whi = g_Whi + (size_t)dir * G4 * DD;
    const __nv_bfloat16* Wlo = g_Wlo + (size_t)dir * G4 * DD;
    const float* bih = dir ? bihb : bihf;
    const float* bhh = dir ? bhhb : bhhf;

    float c[2][4][4];
#pragma unroll
    for (int mi = 0; mi < 2; mi++)
#pragma unroll
        for (int j = 0; j < 4; j++)
#pragma unroll
            for (int q = 0; q < 4; q++) c[mi][j][q] = 0.f;

    uint32_t sbase = smem_u32(dsm);
    int quad = lane >> 3, qr = lane & 7;
    int aRow = warp_m * 32 + (quad & 1) * 8 + qr;
    int colA = (quad >> 1) * 8;
    int bRow0 = warp_n * 32 + (quad >> 1) * 8 + qr;
    int bRow1 = bRow0 + 16;
    int colB = (quad & 1) * 8;

    xg_issue(sbase, 0, gbase, Whi, Wlo, t0, tid);
    cpa_commit();

#pragma unroll 1
    for (int kc = 0; kc < 8; kc++) {
        if (kc < 7) {
            xg_issue(sbase + ((kc + 1) & 1) * XG_BUF, kc + 1, gbase, Whi, Wlo, t0, tid);
            cpa_commit();
            cpa_wait<1>();
        } else {
            cpa_wait<0>();
        }
        __syncthreads();

        uint32_t bb = sbase + (kc & 1) * XG_BUF;
        uint32_t aHi = bb + (uint32_t)(aRow * XG_AROWB + colA * 2);
        uint32_t aLo = aHi + 18432;
        uint32_t bHi0 = bb + 36864 + (uint32_t)(bRow0 * XG_AROWB + colB * 2);
        uint32_t bHi1 = bb + 36864 + (uint32_t)(bRow1 * XG_AROWB + colB * 2);
        uint32_t bLo0 = bHi0 + 9216;
        uint32_t bLo1 = bHi1 + 9216;

#pragma unroll
        for (int ks = 0; ks < 4; ks++) {
            uint32_t ah0[4], ah1[4], al0[4], al1[4];
            uint32_t bh0[4], bh1[4], bl0[4], bl1[4];
            ldsm4(ah0, aHi + ks * 32);
            ldsm4(ah1, aHi + 2304 + ks * 32);
            ldsm4(al0, aLo + ks * 32);
            ldsm4(al1, aLo + 2304 + ks * 32);
            ldsm4(bh0, bHi0 + ks * 32);
            ldsm4(bh1, bHi1 + ks * 32);
            ldsm4(bl0, bLo0 + ks * 32);
            ldsm4(bl1, bLo1 + ks * 32);
#pragma unroll
            for (int j = 0; j < 4; j++) {
                const uint32_t* Bh = ((j < 2) ? bh0 : bh1) + (j & 1) * 2;
                const uint32_t* Bl = ((j < 2) ? bl0 : bl1) + (j & 1) * 2;
                mma16816(c[0][j], ah0, Bh);
                mma16816(c[0][j], ah0, Bl);
                mma16816(c[0][j], al0, Bh);
                mma16816(c[1][j], ah1, Bh);
                mma16816(c[1][j], ah1, Bl);
                mma16816(c[1][j], al1, Bh);
            }
        }
        __syncthreads();
    }

    int t = t0 + warp_n;
    float* outp = g_xg + (((size_t)dir * TT + t) * G4 + gbase + warp_m * 32) * 32;
    int tig = lane & 3, grp = lane >> 2;
#pragma unroll
    for (int mi = 0; mi < 2; mi++) {
        int m0 = mi * 16 + grp;
        int gg = gbase + warp_m * 32 + m0;
        float bia0 = bih[gg] + bhh[gg];
        float bia1 = bih[gg + 8] + bhh[gg + 8];
#pragma unroll
        for (int j = 0; j < 4; j++) {
            int b = j * 8 + tig * 2;
            float2 v0 = make_float2(c[mi][j][0] + bia0, c[mi][j][1] + bia0);
            float2 v1 = make_float2(c[mi][j][2] + bia1, c[mi][j][3] + bia1);
            __stcs((float2*)(outp + (size_t)m0 * 32 + b), v0);
            __stcs((float2*)(outp + (size_t)(m0 + 8) * 32 + b), v1);
        }
    }
}

// ---------------------------------------------------------------------------
// rec_kernel (R9 structure): 128 blocks x 256 threads. Block = (dir, 8 units
// = 32 gate rows r=g*8+u). Warp w = K-slice [64w,64w+64); W_hh bf16 hi/lo
// fragments register-resident. h exchange: double-buffered bf16 hi/lo
// [b][512] in L2, block-wide staging, global per-step flag barrier.
// Deltas vs R9: publisher-scoped fence; reduce merged into pointwise.
// smem: h staging 2x33280 | sC 8x32x40 f32.
// ---------------------------------------------------------------------------
#define HSTR 1040
#define HREG 33280
#define SC_OFF 66560

__global__ void __launch_bounds__(256, 1)
rec_kernel(const int* __restrict__ lengths, float* __restrict__ out) {
    extern __shared__ unsigned char sm[];
    float* sC = (float*)(sm + SC_OFF);     // [8][32][40]
    __shared__ __nv_bfloat16 sPub[2][32][8];
    __shared__ float sOut[32][8];

    int blk = blockIdx.x;
    int dir = blk >> 6;
    int jbase = (blk & 63) * 8;
    int tid = threadIdx.x, wid = tid >> 5, lane = tid & 31;
    int quad = lane >> 3, qr = lane & 7;
    uint32_t sbase = smem_u32(sm);

    // ---- prologue: stage W_hh rows (hi @0, lo @HREG), load A fragments ----
    {
        const __nv_bfloat16* Hhi = g_Hhi + (size_t)dir * G4 * HH;
        const __nv_bfloat16* Hlo = g_Hlo + (size_t)dir * G4 * HH;
        for (int i = tid; i < 2048; i += 256) {
            int row = i >> 6, ch = i & 63;
            int g = row >> 3, u = row & 7;
            size_t src = (size_t)(g * 512 + jbase + u) * HH + ch * 8;
            *(float4*)(sm + row * HSTR + ch * 16) = *(const float4*)(Hhi + src);
            *(float4*)(sm + HREG + row * HSTR + ch * 16) = *(const float4*)(Hlo + src);
        }
    }
    __syncthreads();

    uint32_t ahi[2][4][4], alo[2][4][4];
#pragma unroll
    for (int mi = 0; mi < 2; mi++) {
#pragma unroll
        for (int kt = 0; kt < 4; kt++) {
            int aRow = mi * 16 + (quad & 1) * 8 + qr;
            int colA = wid * 64 + kt * 16 + (quad >> 1) * 8;
            ldsm4(ahi[mi][kt], sbase + (uint32_t)(aRow * HSTR + colA * 2));
            ldsm4(alo[mi][kt], sbase + HREG + (uint32_t)(aRow * HSTR + colA * 2));
        }
    }
    __syncthreads();

    int mylen = lengths[lane];
    int j = jbase + wid;                    // pointwise identity (unit, batch)
    float cc = 0.f, hh = 0.f;
    const float* xgd = g_xg + (size_t)dir * TT * G4 * 32;
    int bRow0 = (quad >> 1) * 8 + qr;
    int colB = (quad & 1) * 8;
    int grp = lane >> 2, tig = lane & 3;

    for (int s = 0; s < TT; s++) {
        int t = dir ? (TT - 1 - s) : s;
        int buf = s & 1;

        // xg prefetch for pointwise
        const float* xgt = xgd + (size_t)t * G4 * 32;
        float xv0 = __ldcs(xgt + (size_t)(0 * HH + j) * 32 + lane);
        float xv1 = __ldcs(xgt + (size_t)(1 * HH + j) * 32 + lane);
        float xv2 = __ldcs(xgt + (size_t)(2 * HH + j) * 32 + lane);
        float xv3 = __ldcs(xgt + (size_t)(3 * HH + j) * 32 + lane);

        // stage h hi/lo [b][512] -> smem (padded rows), block-wide
        {
            const __nv_bfloat16* hs = g_hb + (size_t)(buf * 2 + dir) * 2 * 16384;
#pragma unroll
            for (int i = tid; i < 4096; i += 256) {
                int split = i >> 11, idx = i & 2047;
                int row = idx >> 6, ch = idx & 63;
                cpa16(sbase + split * HREG + (uint32_t)(row * HSTR + ch * 16),
                      hs + (size_t)split * 16384 + row * 512 + ch * 8);
            }
            cpa_commit();
            cpa_wait<0>();
        }
        __syncthreads();

        // MMA: warp's K-slice, 3-split
        float cf[2][4][4];
#pragma unroll
        for (int mi = 0; mi < 2; mi++)
#pragma unroll
            for (int jj = 0; jj < 4; jj++)
#pragma unroll
                for (int q = 0; q < 4; q++) cf[mi][jj][q] = 0.f;

#pragma unroll
        for (int kt = 0; kt < 4; kt++) {
            uint32_t ba = sbase + (uint32_t)(bRow0 * HSTR
                          + (wid * 64 + kt * 16 + colB) * 2);
            uint32_t bh0[4], bh1[4], bl0[4], bl1[4];
            ldsm4(bh0, ba);
            ldsm4(bh1, ba + 16 * HSTR);
            ldsm4(bl0, ba + HREG);
            ldsm4(bl1, ba + HREG + 16 * HSTR);
#pragma unroll
            for (int jj = 0; jj < 4; jj++) {
                const uint32_t* Bh = ((jj < 2) ? bh0 : bh1) + (jj & 1) * 2;
                const uint32_t* Bl = ((jj < 2) ? bl0 : bl1) + (jj & 1) * 2;
                mma16816(cf[0][jj], ahi[0][kt], Bh);
                mma16816(cf[0][jj], ahi[0][kt], Bl);
                mma16816(cf[0][jj], alo[0][kt], Bh);
                mma16816(cf[1][jj], ahi[1][kt], Bh);
                mma16816(cf[1][jj], ahi[1][kt], Bl);
                mma16816(cf[1][jj], alo[1][kt], Bh);
            }
        }

        // store partials sC[w][m][40]
        {
            float* cw = sC + wid * 1280;
#pragma unroll
            for (int mi = 0; mi < 2; mi++) {
#pragma unroll
                for (int jj = 0; jj < 4; jj++) {
                    int m0 = mi * 16 + grp, n0 = jj * 8 + tig * 2;
                    cw[m0 * 40 + n0]           = cf[mi][jj][0];
                    cw[m0 * 40 + n0 + 1]       = cf[mi][jj][1];
                    cw[(m0 + 8) * 40 + n0]     = cf[mi][jj][2];
                    cw[(m0 + 8) * 40 + n0 + 1] = cf[mi][jj][3];
                }
            }
        }
        __syncthreads();

        // pointwise with merged 8-way reduce (thread = (unit wid, batch lane))
        {
            float a0 = 0.f, a1 = 0.f, a2 = 0.f, a3 = 0.f;
#pragma unroll
            for (int w2 = 0; w2 < 8; w2++) {
                const float* cw = sC + w2 * 1280;
                a0 += cw[(0 * 8 + wid) * 40 + lane];
                a1 += cw[(1 * 8 + wid) * 40 + lane];
                a2 += cw[(2 * 8 + wid) * 40 + lane];
                a3 += cw[(3 * 8 + wid) * 40 + lane];
            }
            float gi = sigmoidf_(a0 + xv0);
            float gf = sigmoidf_(a1 + xv1);
            float gg = tanhf   (a2 + xv2);
            float go = sigmoidf_(a3 + xv3);
            float cn = gf * cc + gi * gg;
            float hn = go * tanhf(cn);
            if (t < mylen) { cc = cn; hh = hn; }
            __nv_bfloat16 hi = __float2bfloat16(hh);
            sPub[0][lane][wid] = hi;
            sPub[1][lane][wid] = __float2bfloat16(hh - __bfloat162float(hi));
            sOut[lane][wid] = hh;
        }
        __syncthreads();

        // publish h into write buffer; publishers fence their own stores
        if (tid < 64) {
            int split = tid >> 5, b = tid & 31;
            __stcg((float4*)(g_hb + (size_t)((buf ^ 1) * 2 + dir) * 2 * 16384
                             + (size_t)split * 16384 + b * 512 + jbase),
                   *(float4*)&sPub[split][b][0]);
            __threadfence();
        }
        __syncthreads();
        if (tid == 0) ((volatile int*)g_flags)[blk] = s + 1;
        if (tid >= 64 && tid < 128) {
            int idx = tid - 64;
            int b = idx >> 1, half = idx & 1;
            float4 v;
            v.x = sOut[b][half * 4 + 0]; v.y = sOut[b][half * 4 + 1];
            v.z = sOut[b][half * 4 + 2]; v.w = sOut[b][half * 4 + 3];
            *(float4*)(out + ((size_t)(b * TT + t)) * 1024 + dir * HH + jbase + half * 4) = v;
        }
        if (tid < 64) {
            volatile int* f = (volatile int*)&g_flags[dir * 64 + tid];
            while (*f < s + 1) { }
        }
        __syncthreads();
    }
}

// ---------------------------------------------------------------------------
extern "C" void kernel_launch(void* const* d_in, const int* in_sizes, int n_in,
                              void* d_out, int out_size) {
    const float* x      = (const float*)d_in[0];
    const int*   lens   = (const int*)  d_in[1];
    const float* W_ih_f = (const float*)d_in[2];
    const float* W_hh_f = (const float*)d_in[3];
    const float* b_ih_f = (const float*)d_in[4];
    const float* b_hh_f = (const float*)d_in[5];
    const float* W_ih_b = (const float*)d_in[6];
    const float* W_hh_b = (const float*)d_in[7];
    const float* b_ih_b = (const float*)d_in[8];
    const float* b_hh_b = (const float*)d_in[9];
    float* out = (float*)d_out;

    cudaFuncSetAttribute(xg_mma,     cudaFuncAttributeMaxDynamicSharedMemorySize, 2 * XG_BUF);
    cudaFuncSetAttribute(rec_kernel, cudaFuncAttributeMaxDynamicSharedMemorySize, 131072);

    init_kernel<<<256, 256>>>();
    prep_w<<<(2 * G4 * DD + 255) / 256, 256>>>(W_ih_f, W_ih_b);
    prep_whh<<<(2 * G4 * HH + 255) / 256, 256>>>(W_hh_f, W_hh_b);
    prep_x<<<(BB * TT * DD + 255) / 256, 256>>>(x);
    xg_mma<<<dim3(256, 32), 256, 2 * XG_BUF>>>(b_ih_f, b_hh_f, b_ih_b, b_hh_b);
    rec_kernel<<<NBLK, 256, 131072>>>(lens, out);
}

// round 16
// speedup vs baseline: 1.7152x; 1.6533x over previous
#include <cuda_runtime.h>
#include <cuda_bf16.h>
#include <math.h>
#include <stdint.h>

// ---------------------------------------------------------------------------
// BiLSTM: B=32, T=512, D=512, H=512.
//   prep_w / prep_whh / prep_x: bf16 split (hi + lo)
//   xg_mma: HMMA bf16 3-split GEMM -> g_xg[dir][t][g][b]      (R8, passing)
//   rec_kernel: R9 structure EXACTLY, with flags padded to one 128B line
//               each + bounded-backoff polling (anti-contention).
// ---------------------------------------------------------------------------

#define BB 32
#define TT 512
#define DD 512
#define HH 512
#define G4 2048
#define NBLK 128

typedef unsigned long long ull;

__device__ float g_xg[(size_t)2 * TT * G4 * BB];      // [dir][t][g][b]
__device__ __nv_bfloat16 g_hb[2 * 2 * 2 * 32 * 512];  // [buf][dir][split][b][512]
__device__ int   g_flags[NBLK * 32];                  // one 128B line per block
__device__ __nv_bfloat16 g_Whi[(size_t)2 * G4 * DD];
__device__ __nv_bfloat16 g_Wlo[(size_t)2 * G4 * DD];
__device__ __nv_bfloat16 g_Hhi[(size_t)2 * G4 * HH];
__device__ __nv_bfloat16 g_Hlo[(size_t)2 * G4 * HH];
__device__ __nv_bfloat16 g_xhi[(size_t)BB * TT * DD];
__device__ __nv_bfloat16 g_xlo[(size_t)BB * TT * DD];

__device__ __forceinline__ float sigmoidf_(float x) {
    return 1.0f / (1.0f + expf(-x));
}
__device__ __forceinline__ void cpa16(uint32_t s, const void* g) {
    asm volatile("cp.async.cg.shared.global [%0], [%1], 16;" :: "r"(s), "l"(g));
}
__device__ __forceinline__ void cpa_commit() {
    asm volatile("cp.async.commit_group;");
}
template <int N> __device__ __forceinline__ void cpa_wait() {
    asm volatile("cp.async.wait_group %0;" :: "n"(N));
}
__device__ __forceinline__ uint32_t smem_u32(const void* p) {
    return (uint32_t)__cvta_generic_to_shared(p);
}
__device__ __forceinline__ void ldsm4(uint32_t* r, uint32_t a) {
    asm volatile("ldmatrix.sync.aligned.m8n8.x4.shared.b16 {%0,%1,%2,%3}, [%4];"
                 : "=r"(r[0]), "=r"(r[1]), "=r"(r[2]), "=r"(r[3]) : "r"(a));
}
__device__ __forceinline__ void mma16816(float* c, const uint32_t* a,
                                         const uint32_t* b) {
    asm volatile(
        "mma.sync.aligned.m16n8k16.row.col.f32.bf16.bf16.f32 "
        "{%0,%1,%2,%3}, {%4,%5,%6,%7}, {%8,%9}, {%0,%1,%2,%3};"
        : "+f"(c[0]), "+f"(c[1]), "+f"(c[2]), "+f"(c[3])
        : "r"(a[0]), "r"(a[1]), "r"(a[2]), "r"(a[3]), "r"(b[0]), "r"(b[1]));
}

// ---------------------------------------------------------------------------
__global__ void init_kernel() {
    int i = blockIdx.x * blockDim.x + threadIdx.x;
    if (i < NBLK * 32) g_flags[i] = 0;
    ((uint32_t*)g_hb)[i] = 0u;   // 65536 words exactly (256x256 grid)
}

// ---------------------------------------------------------------------------
// bf16 split preps
// ---------------------------------------------------------------------------
__global__ void prep_w(const float* __restrict__ Wf, const float* __restrict__ Wb) {
    size_t i = (size_t)blockIdx.x * 256 + threadIdx.x;
    const size_t half = (size_t)G4 * DD;
    if (i >= 2 * half) return;
    float w = (i < half) ? Wf[i] : Wb[i - half];
    __nv_bfloat16 hi = __float2bfloat16(w);
    g_Whi[i] = hi;
    g_Wlo[i] = __float2bfloat16(w - __bfloat162float(hi));
}
__global__ void prep_whh(const float* __restrict__ Wf, const float* __restrict__ Wb) {
    size_t i = (size_t)blockIdx.x * 256 + threadIdx.x;
    const size_t half = (size_t)G4 * HH;
    if (i >= 2 * half) return;
    float w = (i < half) ? Wf[i] : Wb[i - half];
    __nv_bfloat16 hi = __float2bfloat16(w);
    g_Hhi[i] = hi;
    g_Hlo[i] = __float2bfloat16(w - __bfloat162float(hi));
}
__global__ void prep_x(const float* __restrict__ x) {
    size_t i = (size_t)blockIdx.x * 256 + threadIdx.x;
    if (i >= (size_t)BB * TT * DD) return;
    float v = x[i];
    __nv_bfloat16 hi = __float2bfloat16(v);
    g_xhi[i] = hi;
    g_xlo[i] = __float2bfloat16(v - __bfloat162float(hi));
}

// ---------------------------------------------------------------------------
// xg_mma (R8 version, passing): block = 128 gates x 64 N (2t x 32b), K=512.
// ---------------------------------------------------------------------------
#define XG_BUF 55296
#define XG_AROWB 144

__device__ __forceinline__ void xg_issue(uint32_t bbase, int kc, int gbase,
                                         const __nv_bfloat16* __restrict__ Whi,
                                         const __nv_bfloat16* __restrict__ Wlo,
                                         int t0, int tid) {
    int k0 = kc * 64;
#pragma unroll
    for (int i = tid; i < 3072; i += 256) {
        if (i < 2048) {
            int split = i >> 10, idx = i & 1023;
            int row = idx >> 3, seg = idx & 7;
            const __nv_bfloat16* src =
                (split ? Wlo : Whi) + (size_t)(gbase + row) * DD + k0 + seg * 8;
            cpa16(bbase + split * 18432 + row * XG_AROWB + seg * 16, src);
        } else {
            int j = i - 2048;
            int split = j >> 9, idx = j & 511;
            int row = idx >> 3, seg = idx & 7;
            int t = t0 + (row >> 5), b = row & 31;
            const __nv_bfloat16* src =
                (split ? g_xlo : g_xhi) + ((size_t)b * TT + t) * DD + k0 + seg * 8;
            cpa16(bbase + 36864 + split * 9216 + row * XG_AROWB + seg * 16, src);
        }
    }
}

__global__ void __launch_bounds__(256, 1)
xg_mma(const float* __restrict__ bihf, const float* __restrict__ bhhf,
       const float* __restrict__ bihb, const float* __restrict__ bhhb) {
    extern __shared__ unsigned char dsm[];
    int tid = threadIdx.x, wid = tid >> 5, lane = tid & 31;
    int nt = blockIdx.x, mb = blockIdx.y;
    int dir = mb >> 4, gbase = (mb & 15) * 128;
    int t0 = nt * 2;
    int warp_m = wid >> 1, warp_n = wid & 1;
    const __nv_bfloat16* Whi = g_Whi + (size_t)dir * G4 * DD;
    const __nv_bfloat16* Wlo = g_Wlo + (size_t)dir * G4 * DD;
    const float* bih = dir ? bihb : bihf;
    const float* bhh = dir ? bhhb : bhhf;

    float c[2][4][4];
#pragma unroll
    for (int mi = 0; mi < 2; mi++)
#pragma unroll
        for (int j = 0; j < 4; j++)
#pragma unroll
            for (int q = 0; q < 4; q++) c[mi][j][q] = 0.f;

    uint32_t sbase = smem_u32(dsm);
    int quad = lane >> 3, qr = lane & 7;
    int aRow = warp_m * 32 + (quad & 1) * 8 + qr;
    int colA = (quad >> 1) * 8;
    int bRow0 = warp_n * 32 + (quad >> 1) * 8 + qr;
    int bRow1 = bRow0 + 16;
    int colB = (quad & 1) * 8;

    xg_issue(sbase, 0, gbase, Whi, Wlo, t0, tid);
    cpa_commit();

#pragma unroll 1
    for (int kc = 0; kc < 8; kc++) {
        if (kc < 7) {
            xg_issue(sbase + ((kc + 1) & 1) * XG_BUF, kc + 1, gbase, Whi, Wlo, t0, tid);
            cpa_commit();
            cpa_wait<1>();
        } else {
            cpa_wait<0>();
        }
        __syncthreads();

        uint32_t bb = sbase + (kc & 1) * XG_BUF;
        uint32_t aHi = bb + (uint32_t)(aRow * XG_AROWB + colA * 2);
        uint32_t aLo = aHi + 18432;
        uint32_t bHi0 = bb + 36864 + (uint32_t)(bRow0 * XG_AROWB + colB * 2);
        uint32_t bHi1 = bb + 36864 + (uint32_t)(bRow1 * XG_AROWB + colB * 2);
        uint32_t bLo0 = bHi0 + 9216;
        uint32_t bLo1 = bHi1 + 9216;

#pragma unroll
        for (int ks = 0; ks < 4; ks++) {
            uint32_t ah0[4], ah1[4], al0[4], al1[4];
            uint32_t bh0[4], bh1[4], bl0[4], bl1[4];
            ldsm4(ah0, aHi + ks * 32);
            ldsm4(ah1, aHi + 2304 + ks * 32);
            ldsm4(al0, aLo + ks * 32);
            ldsm4(al1, aLo + 2304 + ks * 32);
            ldsm4(bh0, bHi0 + ks * 32);
            ldsm4(bh1, bHi1 + ks * 32);
            ldsm4(bl0, bLo0 + ks * 32);
            ldsm4(bl1, bLo1 + ks * 32);
#pragma unroll
            for (int j = 0; j < 4; j++) {
                const uint32_t* Bh = ((j < 2) ? bh0 : bh1) + (j & 1) * 2;
                const uint32_t* Bl = ((j < 2) ? bl0 : bl1) + (j & 1) * 2;
                mma16816(c[0][j], ah0, Bh);
                mma16816(c[0][j], ah0, Bl);
                mma16816(c[0][j], al0, Bh);
                mma16816(c[1][j], ah1, Bh);
                mma16816(c[1][j], ah1, Bl);
                mma16816(c[1][j], al1, Bh);
            }
        }
        __syncthreads();
    }

    int t = t0 + warp_n;
    float* outp = g_xg + (((size_t)dir * TT + t) * G4 + gbase + warp_m * 32) * 32;
    int tig = lane & 3, grp = lane >> 2;
#pragma unroll
    for (int mi = 0; mi < 2; mi++) {
        int m0 = mi * 16 + grp;
        int gg = gbase + warp_m * 32 + m0;
        float bia0 = bih[gg] + bhh[gg];
        float bia1 = bih[gg + 8] + bhh[gg + 8];
#pragma unroll
        for (int j = 0; j < 4; j++) {
            int b = j * 8 + tig * 2;
            float2 v0 = make_float2(c[mi][j][0] + bia0, c[mi][j][1] + bia0);
            float2 v1 = make_float2(c[mi][j][2] + bia1, c[mi][j][3] + bia1);
            __stcs((float2*)(outp + (size_t)m0 * 32 + b), v0);
            __stcs((float2*)(outp + (size_t)(m0 + 8) * 32 + b), v1);
        }
    }
}

// ---------------------------------------------------------------------------
// rec_kernel: R9 structure EXACTLY (global barrier, double-buffered h,
// block-wide staging, 2-phase sG reduce, all-thread fence). Only delta:
// per-block flags padded to one 128B L2 line each + backoff in the poll.
// smem: h staging 2x33280 | sC 8x32x40 f32 | sG 32x32 f32.
// ---------------------------------------------------------------------------
#define HSTR 1040
#define HREG 33280
#define SC_OFF 66560
#define SG_OFF (66560 + 40960)

__global__ void __launch_bounds__(256, 1)
rec_kernel(const int* __restrict__ lengths, float* __restrict__ out) {
    extern __shared__ unsigned char sm[];
    float* sC = (float*)(sm + SC_OFF);     // [8][32][40]
    float* sG = (float*)(sm + SG_OFF);     // [32][32]
    __shared__ __nv_bfloat16 sPub[2][32][8];
    __shared__ float sOut[32][8];

    int blk = blockIdx.x;
    int dir = blk >> 6;
    int jbase = (blk & 63) * 8;
    int tid = threadIdx.x, wid = tid >> 5, lane = tid & 31;
    int quad = lane >> 3, qr = lane & 7;
    uint32_t sbase = smem_u32(sm);

    // ---- prologue: stage W_hh rows (hi @0, lo @HREG), load A fragments ----
    {
        const __nv_bfloat16* Hhi = g_Hhi + (size_t)dir * G4 * HH;
        const __nv_bfloat16* Hlo = g_Hlo + (size_t)dir * G4 * HH;
        for (int i = tid; i < 2048; i += 256) {
            int row = i >> 6, ch = i & 63;
            int g = row >> 3, u = row & 7;
            size_t src = (size_t)(g * 512 + jbase + u) * HH + ch * 8;
            *(float4*)(sm + row * HSTR + ch * 16) = *(const float4*)(Hhi + src);
            *(float4*)(sm + HREG + row * HSTR + ch * 16) = *(const float4*)(Hlo + src);
        }
    }
    __syncthreads();

    uint32_t ahi[2][4][4], alo[2][4][4];
#pragma unroll
    for (int mi = 0; mi < 2; mi++) {
#pragma unroll
        for (int kt = 0; kt < 4; kt++) {
            int aRow = mi * 16 + (quad & 1) * 8 + qr;
            int colA = wid * 64 + kt * 16 + (quad >> 1) * 8;
            ldsm4(ahi[mi][kt], sbase + (uint32_t)(aRow * HSTR + colA * 2));
            ldsm4(alo[mi][kt], sbase + HREG + (uint32_t)(aRow * HSTR + colA * 2));
        }
    }
    __syncthreads();

    int mylen = lengths[lane];
    int j = jbase + wid;                    // pointwise identity (unit, batch)
    float cc = 0.f, hh = 0.f;
    const float* xgd = g_xg + (size_t)dir * TT * G4 * 32;
    int bRow0 = (quad >> 1) * 8 + qr;
    int colB = (quad & 1) * 8;
    int grp = lane >> 2, tig = lane & 3;

    for (int s = 0; s < TT; s++) {
        int t = dir ? (TT - 1 - s) : s;
        int buf = s & 1;

        // xg prefetch for pointwise
        const float* xgt = xgd + (size_t)t * G4 * 32;
        float xv0 = __ldcs(xgt + (size_t)(0 * HH + j) * 32 + lane);
        float xv1 = __ldcs(xgt + (size_t)(1 * HH + j) * 32 + lane);
        float xv2 = __ldcs(xgt + (size_t)(2 * HH + j) * 32 + lane);
        float xv3 = __ldcs(xgt + (size_t)(3 * HH + j) * 32 + lane);

        // stage h hi/lo [b][512] -> smem (padded rows), block-wide
        {
            const __nv_bfloat16* hs = g_hb + (size_t)(buf * 2 + dir) * 2 * 16384;
#pragma unroll
            for (int i = tid; i < 4096; i += 256) {
                int split = i >> 11, idx = i & 2047;
                int row = idx >> 6, ch = idx & 63;
                cpa16(sbase + split * HREG + (uint32_t)(row * HSTR + ch * 16),
                      hs + (size_t)split * 16384 + row * 512 + ch * 8);
            }
            cpa_commit();
            cpa_wait<0>();
        }
        __syncthreads();

        // MMA: warp's K-slice, 3-split
        float cf[2][4][4];
#pragma unroll
        for (int mi = 0; mi < 2; mi++)
#pragma unroll
            for (int jj = 0; jj < 4; jj++)
#pragma unroll
                for (int q = 0; q < 4; q++) cf[mi][jj][q] = 0.f;

#pragma unroll
        for (int kt = 0; kt < 4; kt++) {
            uint32_t ba = sbase + (uint32_t)(bRow0 * HSTR
                          + (wid * 64 + kt * 16 + colB) * 2);
            uint32_t bh0[4], bh1[4], bl0[4], bl1[4];
            ldsm4(bh0, ba);
            ldsm4(bh1, ba + 16 * HSTR);
            ldsm4(bl0, ba + HREG);
            ldsm4(bl1, ba + HREG + 16 * HSTR);
#pragma unroll
            for (int jj = 0; jj < 4; jj++) {
                const uint32_t* Bh = ((jj < 2) ? bh0 : bh1) + (jj & 1) * 2;
                const uint32_t* Bl = ((jj < 2) ? bl0 : bl1) + (jj & 1) * 2;
                mma16816(cf[0][jj], ahi[0][kt], Bh);
                mma16816(cf[0][jj], ahi[0][kt], Bl);
                mma16816(cf[0][jj], alo[0][kt], Bh);
                mma16816(cf[1][jj], ahi[1][kt], Bh);
                mma16816(cf[1][jj], ahi[1][kt], Bl);
                mma16816(cf[1][jj], alo[1][kt], Bh);
            }
        }

        // store partials sC[w][m][40]
        {
            float* cw = sC + wid * 1280;
#pragma unroll
            for (int mi = 0; mi < 2; mi++) {
#pragma unroll
                for (int jj = 0; jj < 4; jj++) {
                    int m0 = mi * 16 + grp, n0 = jj * 8 + tig * 2;
                    cw[m0 * 40 + n0]           = cf[mi][jj][0];
                    cw[m0 * 40 + n0 + 1]       = cf[mi][jj][1];
                    cw[(m0 + 8) * 40 + n0]     = cf[mi][jj][2];
                    cw[(m0 + 8) * 40 + n0 + 1] = cf[mi][jj][3];
                }
            }
        }
        __syncthreads();

        // reduce 8 K-slices -> sG[32][32]
        {
            int rm = tid >> 3, rb = (tid & 7) * 4;
            float4 a = *(float4*)(sC + rm * 40 + rb);
#pragma unroll
            for (int w2 = 1; w2 < 8; w2++) {
                float4 p = *(float4*)(sC + w2 * 1280 + rm * 40 + rb);
                a.x += p.x; a.y += p.y; a.z += p.z; a.w += p.w;
            }
            *(float4*)(sG + rm * 32 + rb) = a;
        }
        __syncthreads();

        // pointwise (thread (wid=unit, lane=batch))
        {
            float gi = sigmoidf_(sG[(0 * 8 + wid) * 32 + lane] + xv0);
            float gf = sigmoidf_(sG[(1 * 8 + wid) * 32 + lane] + xv1);
            float gg = tanhf   (sG[(2 * 8 + wid) * 32 + lane] + xv2);
            float go = sigmoidf_(sG[(3 * 8 + wid) * 32 + lane] + xv3);
            float cn = gf * cc + gi * gg;
            float hn = go * tanhf(cn);
            if (t < mylen) { cc = cn; hh = hn; }
            __nv_bfloat16 hi = __float2bfloat16(hh);
            sPub[0][lane][wid] = hi;
            sPub[1][lane][wid] = __float2bfloat16(hh - __bfloat162float(hi));
            sOut[lane][wid] = hh;
        }
        __syncthreads();

        // publish h (16B per (split,b) row) then release
        if (tid < 64) {
            int split = tid >> 5, b = tid & 31;
            __stcg((float4*)(g_hb + (size_t)((buf ^ 1) * 2 + dir) * 2 * 16384
                             + (size_t)split * 16384 + b * 512 + jbase),
                   *(float4*)&sPub[split][b][0]);
        }
        __threadfence();
        __syncthreads();
        if (tid == 0) ((volatile int*)g_flags)[blk * 32] = s + 1;
        if (tid >= 64 && tid < 128) {
            int idx = tid - 64;
            int b = idx >> 1, half = idx & 1;
            float4 v;
            v.x = sOut[b][half * 4 + 0]; v.y = sOut[b][half * 4 + 1];
            v.z = sOut[b][half * 4 + 2]; v.w = sOut[b][half * 4 + 3];
            *(float4*)(out + ((size_t)(b * TT + t)) * 1024 + dir * HH + jbase + half * 4) = v;
        }
        if (tid < 64) {
            volatile int* f = (volatile int*)&g_flags[(dir * 64 + tid) * 32];
            int spins = 0;
            while (*f < s + 1) {
                if (++spins > 8) __nanosleep(64);
            }
        }
        __syncthreads();
    }
}

// ---------------------------------------------------------------------------
extern "C" void kernel_launch(void* const* d_in, const int* in_sizes, int n_in,
                              void* d_out, int out_size) {
    const float* x      = (const float*)d_in[0];
    const int*   lens   = (const int*)  d_in[1];
    const float* W_ih_f = (const float*)d_in[2];
    const float* W_hh_f = (const float*)d_in[3];
    const float* b_ih_f = (const float*)d_in[4];
    const float* b_hh_f = (const float*)d_in[5];
    const float* W_ih_b = (const float*)d_in[6];
    const float* W_hh_b = (const float*)d_in[7];
    const float* b_ih_b = (const float*)d_in[8];
    const float* b_hh_b = (const float*)d_in[9];
    float* out = (float*)d_out;

    cudaFuncSetAttribute(xg_mma,     cudaFuncAttributeMaxDynamicSharedMemorySize, 2 * XG_BUF);
    cudaFuncSetAttribute(rec_kernel, cudaFuncAttributeMaxDynamicSharedMemorySize, 131072);

    init_kernel<<<256, 256>>>();
    prep_w<<<(2 * G4 * DD + 255) / 256, 256>>>(W_ih_f, W_ih_b);
    prep_whh<<<(2 * G4 * HH + 255) / 256, 256>>>(W_hh_f, W_hh_b);
    prep_x<<<(BB * TT * DD + 255) / 256, 256>>>(x);
    xg_mma<<<dim3(256, 32), 256, 2 * XG_BUF>>>(b_ih_f, b_hh_f, b_ih_b, b_hh_b);
    rec_kernel<<<NBLK, 256, 131072>>>(lens, out);
}